// round 5
// baseline (speedup 1.0000x reference)
#include <cuda_runtime.h>
#include <cuda_bf16.h>
#include <cstdint>

// DropEmbedding: out[s,b,:] = W[X[s,b],:] * emb_row_mask(X[s,b]) * lock_mask(b,:)
//   S=2048, B=8, D=1024, V=50257
//
// R5: full async-DMA pipeline (Blackwell cp.async.bulk both directions).
//  - CTA = (b, 32 tokens). One elected thread streams W rows GMEM->SMEM via
//    cp.async.bulk + mbarrier expect_tx (6-deep ring); dropped rows skip the copy.
//  - 256 threads multiply from SMEM, stage the 4KB output row in SMEM.
//  - Output rows leave via cp.async.bulk SMEM->GMEM bulk_group (4 staging bufs).
//  - LSU does only LDS/STS; all GMEM traffic is DMA with deep asynchrony.

#define SEQ_    2048
#define BATCH_  8
#define NINP_   1024
#define ROWB_   4096          // bytes per row (1024 fp32)
#define T_      32            // tokens per CTA
#define DIN_    6             // input ring depth
#define DOUT_   4             // output staging buffers

struct __align__(128) SmemLayout {
    unsigned char in_buf [DIN_][ROWB_];   // 24 KB
    unsigned char out_buf[DOUT_][ROWB_];  // 16 KB
    uint64_t      full[DIN_];             // mbarriers
    int           tok[T_];
    float         se [T_];
};

__device__ __forceinline__ uint32_t smem_u32(const void* p) {
    uint32_t a;
    asm("{ .reg .u64 t; cvta.to.shared.u64 t, %1; cvt.u32.u64 %0, t; }" : "=r"(a) : "l"(p));
    return a;
}

__device__ __forceinline__ void mbar_init(uint32_t mbar, uint32_t count) {
    asm volatile("mbarrier.init.shared.b64 [%0], %1;" :: "r"(mbar), "r"(count) : "memory");
}
__device__ __forceinline__ void mbar_expect_tx(uint32_t mbar, uint32_t bytes) {
    asm volatile("mbarrier.arrive.expect_tx.shared.b64 _, [%0], %1;" :: "r"(mbar), "r"(bytes) : "memory");
}
__device__ __forceinline__ void mbar_arrive(uint32_t mbar) {
    asm volatile("mbarrier.arrive.shared.b64 _, [%0];" :: "r"(mbar) : "memory");
}
__device__ __forceinline__ void mbar_wait(uint32_t mbar, uint32_t parity) {
    uint32_t done;
    asm volatile(
        "{\n\t.reg .pred p;\n\t"
        "mbarrier.try_wait.parity.acquire.cta.shared::cta.b64 p, [%1], %2;\n\t"
        "selp.b32 %0, 1, 0, p;\n\t}"
        : "=r"(done) : "r"(mbar), "r"(parity) : "memory");
    if (!done) {
        asm volatile(
            "{\n\t.reg .pred P1;\n\t"
            "WL_%=:\n\t"
            "mbarrier.try_wait.parity.acquire.cta.shared::cta.b64 P1, [%0], %1, 0x989680;\n\t"
            "@P1 bra.uni WD_%=;\n\t"
            "bra.uni WL_%=;\n\t"
            "WD_%=:\n\t}"
            :: "r"(mbar), "r"(parity) : "memory");
    }
}
__device__ __forceinline__ void bulk_g2s(uint32_t dst_smem, const void* gsrc,
                                         uint32_t bytes, uint32_t mbar) {
    asm volatile(
        "cp.async.bulk.shared::cluster.global.mbarrier::complete_tx::bytes [%0], [%1], %2, [%3];"
        :: "r"(dst_smem), "l"(gsrc), "r"(bytes), "r"(mbar) : "memory");
}
__device__ __forceinline__ void bulk_s2g(void* gdst, uint32_t src_smem, uint32_t bytes) {
    asm volatile(
        "cp.async.bulk.global.shared::cta.bulk_group [%0], [%1], %2;"
        :: "l"(gdst), "r"(src_smem), "r"(bytes) : "memory");
}

__global__ void __launch_bounds__(256)
drop_embedding_kernel(const int*   __restrict__ X,
                      const float* __restrict__ W,
                      const float* __restrict__ u_embed,
                      const float* __restrict__ u_lock,
                      float*       __restrict__ out)
{
    constexpr float KEEP_E     = 1.0f - 0.1f;
    constexpr float KEEP_I     = 1.0f - 0.65f;
    constexpr float INV_KEEP_E = 1.0f / KEEP_E;
    constexpr float INV_KEEP_I = 1.0f / KEEP_I;

    __shared__ SmemLayout sm;

    const int b   = blockIdx.y;
    const int s0  = blockIdx.x * T_;
    const int tid = threadIdx.x;            // 0..255 -> float4 lane over D=1024

    // Resolve tokens + row-dropout scales
    if (tid < T_) {
        const int tok = __ldg(&X[(s0 + tid) * BATCH_ + b]);
        sm.tok[tid] = tok;
        const float ue = __ldg(&u_embed[tok]);
        sm.se[tid] = (ue < KEEP_E) ? INV_KEEP_E : 0.0f;
    }
    if (tid == 0) {
#pragma unroll
        for (int s = 0; s < DIN_; s++) mbar_init(smem_u32(&sm.full[s]), 1);
    }
    __syncthreads();

    // Locked-dropout factors for (b, this lane) — once per thread
    const float4 l = __ldg((const float4*)(u_lock + (size_t)b * NINP_) + tid);
    float4 lm;
    lm.x = (l.x < KEEP_I) ? INV_KEEP_I : 0.0f;
    lm.y = (l.y < KEEP_I) ? INV_KEEP_I : 0.0f;
    lm.z = (l.z < KEEP_I) ? INV_KEEP_I : 0.0f;
    lm.w = (l.w < KEEP_I) ? INV_KEEP_I : 0.0f;

    // Prefill: tokens 0..DIN_-1 (phase 0)
    if (tid == 0) {
#pragma unroll
        for (int s = 0; s < DIN_; s++) {
            const uint32_t fb = smem_u32(&sm.full[s]);
            if (sm.se[s] != 0.0f) {
                mbar_expect_tx(fb, ROWB_);
                bulk_g2s(smem_u32(&sm.in_buf[s][0]),
                         W + (size_t)sm.tok[s] * NINP_, ROWB_, fb);
            } else {
                mbar_arrive(fb);
            }
        }
    }

    for (int k = 0; k < T_; k++) {
        // Free the output staging slot k%DOUT_ (reads of its previous store done)
        if (tid == 0 && k >= DOUT_)
            asm volatile("cp.async.bulk.wait_group.read %0;" :: "n"(DOUT_ - 1) : "memory");
        __syncthreads();   // staging free; last iter's in_buf reads complete

        // Refill: token (k-1)+DIN_ into slot (k-1)%DIN_ (consumed last iteration)
        if (tid == 0 && k >= 1) {
            const int j = k - 1 + DIN_;
            if (j < T_) {
                const int s = (k - 1) % DIN_;
                const uint32_t fb = smem_u32(&sm.full[s]);
                if (sm.se[j] != 0.0f) {
                    mbar_expect_tx(fb, ROWB_);
                    bulk_g2s(smem_u32(&sm.in_buf[s][0]),
                             W + (size_t)sm.tok[j] * NINP_, ROWB_, fb);
                } else {
                    mbar_arrive(fb);
                }
            }
        }

        // Consume token k
        mbar_wait(smem_u32(&sm.full[k % DIN_]), (k / DIN_) & 1);

        const float s = sm.se[k];
        float4 o = make_float4(0.0f, 0.0f, 0.0f, 0.0f);
        if (s != 0.0f) {
            const float4 w = ((const float4*)&sm.in_buf[k % DIN_][0])[tid];
            o.x = w.x * s * lm.x;
            o.y = w.y * s * lm.y;
            o.z = w.z * s * lm.z;
            o.w = w.w * s * lm.w;
        }
        ((float4*)&sm.out_buf[k % DOUT_][0])[tid] = o;

        asm volatile("fence.proxy.async.shared::cta;" ::: "memory");
        __syncthreads();   // staged row complete & fenced for async proxy

        if (tid == 0) {
            bulk_s2g((float*)out + ((size_t)(s0 + k) * BATCH_ + b) * NINP_,
                     smem_u32(&sm.out_buf[k % DOUT_][0]), ROWB_);
            asm volatile("cp.async.bulk.commit_group;" ::: "memory");
        }
    }

    // Drain outstanding bulk stores before exit
    if (tid == 0)
        asm volatile("cp.async.bulk.wait_group %0;" :: "n"(0) : "memory");
}

extern "C" void kernel_launch(void* const* d_in, const int* in_sizes, int n_in,
                              void* d_out, int out_size)
{
    const int*   X  = (const int*)  d_in[0];
    const float* W  = (const float*)d_in[1];
    const float* ue = (const float*)d_in[2];
    const float* ul = (const float*)d_in[3];
    float*       o  = (float*)      d_out;

    (void)in_sizes; (void)n_in; (void)out_size;

    dim3 grid(SEQ_ / T_, BATCH_);   // (64, 8) = 512 CTAs
    dim3 block(256);
    drop_embedding_kernel<<<grid, block>>>(X, W, ue, ul, o);
}